// round 7
// baseline (speedup 1.0000x reference)
#include <cuda_runtime.h>
#include <cstdint>

// ============================================================================
// SparseQuanvLayer: 4-qubit random circuit over strided 2x2x2 patches.
//
// Math reduction: the circuit is a fixed 16x16 unitary U(rand_params). The
// initial product state is REAL, so z_w = psi0^T Q_w psi0 with
// Q_w = Re(U^dagger Z_w U). In the per-wire basis g = (1, cos(pi*phi),
// sin(pi*phi)) this is z_w = h^T M_w k with h = g0 (x) g1, k = g2 (x) g3 and
// M_w a 9x9 coefficient matrix. A one-block setup kernel reconstructs the
// numpy default_rng(42) gate sequence on-device, builds U in fp64, and emits
// the 4x81 float coefficients; the main kernel is then pure ALU.
//
// R6 fix: Generator.shuffle (via permutation(int)) goes through _shuffle_raw,
// which draws j = random_interval(&bitgen, i) — MASKED rejection over
// buffered next_uint32 — not the Lemire path (_shuffle_int/choice only).
// Seed path (ss_mix subtraction) confirmed by the R4->R6 correlation jump.
// ============================================================================

__device__ float d_M[324];  // M_w[r][c], w*81 + r*9 + c

// ---------------- numpy RNG replication (SeedSequence + PCG64 XSL-RR) -------

struct Pcg {
    unsigned __int128 state, inc;
    int has32;
    unsigned int buf32;
};

__device__ __forceinline__ void pcg_step(Pcg& g) {
    const unsigned __int128 mult =
        (((unsigned __int128)0x2360ed051fc65da4ULL) << 64) | 0x4385df649fccf645ULL;
    g.state = g.state * mult + g.inc;
}

__device__ __forceinline__ unsigned long long pcg_next64(Pcg& g) {
    pcg_step(g);  // 128-bit PCG variants step FIRST, output NEW state
    unsigned long long hi = (unsigned long long)(g.state >> 64);
    unsigned long long lo = (unsigned long long)g.state;
    unsigned int rot = (unsigned int)(g.state >> 122);
    unsigned long long x = hi ^ lo;
    return (x >> rot) | (x << ((64u - rot) & 63u));
}

// pcg64_next32: returns low 32 first, buffers high 32 persistently.
__device__ __forceinline__ unsigned int pcg_next32(Pcg& g) {
    if (g.has32) { g.has32 = 0; return g.buf32; }
    unsigned long long v = pcg_next64(g);
    g.has32 = 1;
    g.buf32 = (unsigned int)(v >> 32);
    return (unsigned int)v;
}

__device__ __forceinline__ double rng_double(Pcg& g) {
    return (double)(pcg_next64(g) >> 11) * (1.0 / 9007199254740992.0);
}

// numpy buffered_bounded_lemire_uint32 — used by Generator.integers.
// rng = inclusive max, rng_excl = rng + 1.
__device__ unsigned int lemire32(Pcg& g, unsigned int rng_excl) {
    unsigned long long m = (unsigned long long)pcg_next32(g) * (unsigned long long)rng_excl;
    unsigned int leftover = (unsigned int)m;
    if (leftover < rng_excl) {
        unsigned int threshold = (unsigned int)(0u - rng_excl) % rng_excl;
        while (leftover < threshold) {
            m = (unsigned long long)pcg_next32(g) * (unsigned long long)rng_excl;
            leftover = (unsigned int)m;
        }
    }
    return (unsigned int)(m >> 32);
}

// numpy random_interval (masked rejection, 32-bit path, buffered next_uint32)
// — used by Generator._shuffle_raw, i.e. by shuffle()/permutation().
__device__ unsigned int rand_interval(Pcg& g, unsigned int mx) {
    if (mx == 0) return 0;
    unsigned int mask = mx;
    mask |= mask >> 1; mask |= mask >> 2; mask |= mask >> 4;
    mask |= mask >> 8; mask |= mask >> 16;
    unsigned int v;
    do { v = pcg_next32(g) & mask; } while (v > mx);
    return v;
}

__device__ unsigned int ss_hashmix(unsigned int value, unsigned int& hc) {
    value ^= hc;
    hc *= 0x931e8875u;   // MULT_A
    value *= hc;
    value ^= value >> 16;
    return value;
}

// numpy SeedSequence.mix: result = x*MIX_MULT_L - y*MIX_MULT_R; result ^= result>>16
__device__ unsigned int ss_mix(unsigned int x, unsigned int y) {
    unsigned int r = x * 0xca01f9ddu;   // MIX_MULT_L
    r -= y * 0x4973f715u;               // MIX_MULT_R  (subtract)
    r ^= r >> 16;
    return r;
}

__device__ void pcg_seed42(Pcg& g) {
    // SeedSequence(42), pool_size=4, entropy words = [42]
    unsigned int pool[4];
    unsigned int hc = 0x43b0d7e5u;  // INIT_A
    pool[0] = ss_hashmix(42u, hc);
    pool[1] = ss_hashmix(0u, hc);
    pool[2] = ss_hashmix(0u, hc);
    pool[3] = ss_hashmix(0u, hc);
    for (int src = 0; src < 4; src++)
        for (int dst = 0; dst < 4; dst++)
            if (src != dst)
                pool[dst] = ss_mix(pool[dst], ss_hashmix(pool[src], hc));
    // generate_state(4, uint64) -> 8 uint32 words, little-endian pairs
    unsigned int hb = 0x8b51f9ddu;  // INIT_B
    unsigned long long val[4];
    for (int i = 0; i < 4; i++) {
        unsigned int w32[2];
        for (int h = 0; h < 2; h++) {
            unsigned int dv = pool[(2 * i + h) & 3];
            dv ^= hb;
            hb *= 0x58f38dedu;  // MULT_B
            dv *= hb;
            dv ^= dv >> 16;
            w32[h] = dv;
        }
        val[i] = (unsigned long long)w32[0] | ((unsigned long long)w32[1] << 32);
    }
    // pcg64_set_seed: initstate = (val[0]<<64)|val[1], initseq = (val[2]<<64)|val[3]
    unsigned __int128 initstate = (((unsigned __int128)val[0]) << 64) | val[1];
    unsigned __int128 initseq   = (((unsigned __int128)val[2]) << 64) | val[3];
    g.state = 0;
    g.inc = (initseq << 1) | 1;
    pcg_step(g);
    g.state += initstate;
    pcg_step(g);
    g.has32 = 0;
    g.buf32 = 0;
}

// ---------------- setup kernel: OPS -> U -> Q_w -> M coefficients -----------

#define MAXOPS 64

__global__ void __launch_bounds__(1024) setup_kernel(const float* __restrict__ rp) {
    __shared__ int s_n;
    __shared__ int s_type[MAXOPS], s_a[MAXOPS], s_b[MAXOPS], s_p[MAXOPS];
    __shared__ double Ur[16][16], Ui[16][16];
    __shared__ double Q[4][16][16];
    int t = threadIdx.x;

    if (t == 0) {
        // Reconstruct _random_layer_ops(weights_shape=(1,4), wires=4, ratio=0.3, seed=42)
        Pcg g;
        pcg_seed42(g);
        int i = 0, n = 0;
        while (i < 4 && n < MAXOPS) {
            if (rng_double(g) > 0.3) {
                int kind = (int)lemire32(g, 3u);   // integers(0,3): rng=2, rng_excl=3
                int w    = (int)lemire32(g, 4u);   // integers(0,4): rng=3, rng_excl=4
                s_type[n] = 0; s_a[n] = kind; s_b[n] = w; s_p[n] = i;
                n++; i++;
            } else {
                // permutation(4) = arange(4); Generator.shuffle -> _shuffle_raw:
                //   for i in reversed(range(1, 4)):
                //       j = random_interval(&bitgen, i)   // masked rejection
                //       swap(arr[i], arr[j])
                int arr[4] = {0, 1, 2, 3};
                for (int ii = 3; ii >= 1; ii--) {
                    int jj = (int)rand_interval(g, (unsigned)ii);
                    int tmp = arr[ii]; arr[ii] = arr[jj]; arr[jj] = tmp;
                }
                s_type[n] = 1; s_a[n] = arr[0]; s_b[n] = arr[1]; s_p[n] = 0;
                n++;
            }
        }
        s_n = n;
    }
    // U = identity (16x16 complex, row = output basis state, col = input)
    for (int e = t; e < 256; e += blockDim.x) {
        Ur[e >> 4][e & 15] = ((e >> 4) == (e & 15)) ? 1.0 : 0.0;
        Ui[e >> 4][e & 15] = 0.0;
    }
    __syncthreads();

    int nops = s_n;
    for (int o = 0; o < nops; o++) {
        if (s_type[o] == 0) {
            double th = (double)rp[s_p[o]];
            double ch = cos(0.5 * th), sh = sin(0.5 * th);
            int kind = s_a[o];
            double u00r = ch, u00i = 0, u01r = 0, u01i = 0;
            double u10r = 0,  u10i = 0, u11r = ch, u11i = 0;
            if (kind == 0)      { u01i = -sh; u10i = -sh; }           // RX
            else if (kind == 1) { u01r = -sh; u10r =  sh; }           // RY
            else                { u00i = -sh; u11i =  sh; }           // RZ
            int bit = 1 << (3 - s_b[o]);  // wire w <-> bit (3-w)
            if (t < 128) {
                int pair = t >> 4, col = t & 15;
                int low = pair & (bit - 1);
                int high = (pair ^ low) << 1;
                int s0 = high | low, s1 = s0 | bit;
                double ar = Ur[s0][col], ai = Ui[s0][col];
                double br = Ur[s1][col], bi = Ui[s1][col];
                Ur[s0][col] = u00r * ar - u00i * ai + u01r * br - u01i * bi;
                Ui[s0][col] = u00r * ai + u00i * ar + u01r * bi + u01i * br;
                Ur[s1][col] = u10r * ar - u10i * ai + u11r * br - u11i * bi;
                Ui[s1][col] = u10r * ai + u10i * ar + u11r * bi + u11i * br;
            }
        } else {
            int cb = 1 << (3 - s_a[o]);  // control bit
            int tb = 1 << (3 - s_b[o]);  // target bit
            if (t < 64) {
                int pi = t >> 4, col = t & 15;
                int s0 = cb, rr = pi;
                for (int bp = 0; bp < 4; bp++) {
                    int bb = 1 << bp;
                    if (bb == cb || bb == tb) continue;
                    if (rr & 1) s0 |= bb;
                    rr >>= 1;
                }
                int s1 = s0 | tb;
                double xr = Ur[s0][col], xi = Ui[s0][col];
                Ur[s0][col] = Ur[s1][col]; Ui[s0][col] = Ui[s1][col];
                Ur[s1][col] = xr;          Ui[s1][col] = xi;
            }
        }
        __syncthreads();
    }

    // Q_w[a][b] = sum_s sign_w(s) * Re(conj(U[s,a]) U[s,b])
    for (int task = t; task < 1024; task += blockDim.x) {
        int w = task >> 8, a = (task >> 4) & 15, b = task & 15;
        int bit = 1 << (3 - w);
        double q = 0;
        for (int s = 0; s < 16; s++) {
            double v = Ur[s][a] * Ur[s][b] + Ui[s][a] * Ui[s][b];
            q += (s & bit) ? -v : v;
        }
        Q[w][a][b] = q;
    }
    __syncthreads();

    // Per-wire change of basis {cc,ss,cs} -> {1, cos(pi*phi), sin(pi*phi)}:
    // cc=(1+C)/2, ss=(1-C)/2, cs=sc=S/2. For each m, exactly 2 valid (i,j)
    // per wire, |coef|=1/2, sign -1 only for (m=1, i=j=1).
    for (int task = t; task < 324; task += blockDim.x) {
        int w = task / 81, m = task % 81;
        int mm[4] = { m / 27, (m / 9) % 3, (m / 3) % 3, m % 3 };
        double acc = 0;
        for (int c = 0; c < 16; c++) {
            int a = 0, b = 0;
            double sgn = 1.0;
            #pragma unroll
            for (int k = 0; k < 4; k++) {
                int sel = (c >> k) & 1;
                int mk = mm[k];
                int i_, j_;
                if (mk == 2) { i_ = sel; j_ = 1 - sel; }
                else         { i_ = sel; j_ = sel; if (mk == 1 && sel == 1) sgn = -sgn; }
                int bitp = 3 - k;
                a |= i_ << bitp;
                b |= j_ << bitp;
            }
            acc += sgn * Q[w][a][b];
        }
        d_M[w * 81 + m] = (float)(acc * 0.0625);
    }
}

// ---------------- main kernel: per-element 4x (h^T M_w k) -------------------

__global__ void __launch_bounds__(256) quanv_kernel(const float* __restrict__ x,
                                                    float* __restrict__ out) {
    __shared__ float Ms[324];
    for (int u = threadIdx.x; u < 324; u += 256) Ms[u] = d_M[u];
    __syncthreads();

    int n = blockIdx.x * 256 + threadIdx.x;          // 0 .. 524287
    int kk = n & 31, j = (n >> 5) & 31, i = (n >> 10) & 31, b = n >> 15;
    const float* xb = x + b * 262144;
    int base = i * 8192 + j * 128 + kk * 2;          // (2i)*4096 + (2j)*64 + 2k
    float p0 = xb[base];                             // x[b, 2i,   2j,   2k  ]
    float p1 = xb[base + 4160];                      // x[b, 2i+1, 2j+1, 2k  ]
    float p2 = xb[base + 65];                        // x[b, 2i,   2j+1, 2k+1]
    float p3 = xb[base + 4097];                      // x[b, 2i+1, 2j,   2k+1]

    const float PI = 3.14159265358979323846f;
    float C0, S0, C1, S1, C2, S2, C3, S3;
    __sincosf(PI * p0, &S0, &C0);
    __sincosf(PI * p1, &S1, &C1);
    __sincosf(PI * p2, &S2, &C2);
    __sincosf(PI * p3, &S3, &C3);

    float h[9]  = {1.f, C1, S1, C0, C0 * C1, C0 * S1, S0, S0 * C1, S0 * S1};
    float kv[9] = {1.f, C3, S3, C2, C2 * C3, C2 * S3, S2, S2 * C3, S2 * S3};

    float4 res;
    float* rp = &res.x;
    #pragma unroll
    for (int w = 0; w < 4; w++) {
        float acc = 0.f;
        #pragma unroll
        for (int r = 0; r < 9; r++) {
            float u = 0.f;
            #pragma unroll
            for (int c = 0; c < 9; c++)
                u = fmaf(Ms[w * 81 + r * 9 + c], kv[c], u);
            acc = fmaf(h[r], u, acc);
        }
        rp[w] = acc;
    }
    reinterpret_cast<float4*>(out)[n] = res;
}

// ---------------- launch ----------------------------------------------------

extern "C" void kernel_launch(void* const* d_in, const int* in_sizes, int n_in,
                              void* d_out, int out_size) {
    const float* x;
    const float* rp;
    if (n_in >= 2 && in_sizes[0] == 4) {
        rp = (const float*)d_in[0];
        x  = (const float*)d_in[1];
    } else {
        x  = (const float*)d_in[0];
        rp = (const float*)d_in[1];
    }
    setup_kernel<<<1, 1024>>>(rp);
    quanv_kernel<<<2048, 256>>>(x, (float*)d_out);
}

// round 12
// speedup vs baseline: 6.2643x; 6.2643x over previous
#include <cuda_runtime.h>
#include <cstdint>

// ============================================================================
// SparseQuanvLayer: 4-qubit random circuit over strided 2x2x2 patches.
//
// z_w = h^T M_w k with h = g0 (x) g1, k = g2 (x) g3, g = (1, cos pi*phi,
// sin pi*phi); M_w are 4x81 coefficients derived from the circuit unitary.
//
// R7 -> R8:
//  * Op list (seed-42 numpy RNG replication) moved to HOST, passed by value:
//    removes the ~120us serial/fp64 single-block setup cost.
//  * Device setup is fp32, one 256-thread block (~3us).
//  * Main kernel: 2 elements/thread via packed fma.rn.f32x2; coefficients
//    held duplicated in shared as 64-bit pairs so one LDS.64 + one FFMA2
//    serve both elements. float4 input loads / float4 output stores.
// ============================================================================

// ---------------- numpy RNG replication (host + device capable) -------------

struct Pcg {
    unsigned __int128 state, inc;
    int has32;
    unsigned int buf32;
};

__host__ __device__ __forceinline__ void pcg_step(Pcg& g) {
    const unsigned __int128 mult =
        (((unsigned __int128)0x2360ed051fc65da4ULL) << 64) | 0x4385df649fccf645ULL;
    g.state = g.state * mult + g.inc;
}

__host__ __device__ __forceinline__ unsigned long long pcg_next64(Pcg& g) {
    pcg_step(g);
    unsigned long long hi = (unsigned long long)(g.state >> 64);
    unsigned long long lo = (unsigned long long)g.state;
    unsigned int rot = (unsigned int)(g.state >> 122);
    unsigned long long x = hi ^ lo;
    return (x >> rot) | (x << ((64u - rot) & 63u));
}

__host__ __device__ __forceinline__ unsigned int pcg_next32(Pcg& g) {
    if (g.has32) { g.has32 = 0; return g.buf32; }
    unsigned long long v = pcg_next64(g);
    g.has32 = 1;
    g.buf32 = (unsigned int)(v >> 32);
    return (unsigned int)v;
}

__host__ __device__ __forceinline__ double rng_double(Pcg& g) {
    return (double)(pcg_next64(g) >> 11) * (1.0 / 9007199254740992.0);
}

// Generator.integers -> buffered_bounded_lemire_uint32 (rng_excl = max+1)
__host__ __device__ unsigned int lemire32(Pcg& g, unsigned int rng_excl) {
    unsigned long long m = (unsigned long long)pcg_next32(g) * (unsigned long long)rng_excl;
    unsigned int leftover = (unsigned int)m;
    if (leftover < rng_excl) {
        unsigned int threshold = (unsigned int)(0u - rng_excl) % rng_excl;
        while (leftover < threshold) {
            m = (unsigned long long)pcg_next32(g) * (unsigned long long)rng_excl;
            leftover = (unsigned int)m;
        }
    }
    return (unsigned int)(m >> 32);
}

// Generator.shuffle -> _shuffle_raw -> random_interval (masked rejection)
__host__ __device__ unsigned int rand_interval(Pcg& g, unsigned int mx) {
    if (mx == 0) return 0;
    unsigned int mask = mx;
    mask |= mask >> 1; mask |= mask >> 2; mask |= mask >> 4;
    mask |= mask >> 8; mask |= mask >> 16;
    unsigned int v;
    do { v = pcg_next32(g) & mask; } while (v > mx);
    return v;
}

__host__ __device__ unsigned int ss_hashmix(unsigned int value, unsigned int& hc) {
    value ^= hc;
    hc *= 0x931e8875u;   // MULT_A
    value *= hc;
    value ^= value >> 16;
    return value;
}

// SeedSequence.mix: x*MIX_MULT_L - y*MIX_MULT_R, then xor-shift
__host__ __device__ unsigned int ss_mix(unsigned int x, unsigned int y) {
    unsigned int r = x * 0xca01f9ddu;
    r -= y * 0x4973f715u;
    r ^= r >> 16;
    return r;
}

__host__ __device__ void pcg_seed42(Pcg& g) {
    unsigned int pool[4];
    unsigned int hc = 0x43b0d7e5u;  // INIT_A
    pool[0] = ss_hashmix(42u, hc);
    pool[1] = ss_hashmix(0u, hc);
    pool[2] = ss_hashmix(0u, hc);
    pool[3] = ss_hashmix(0u, hc);
    for (int src = 0; src < 4; src++)
        for (int dst = 0; dst < 4; dst++)
            if (src != dst)
                pool[dst] = ss_mix(pool[dst], ss_hashmix(pool[src], hc));
    unsigned int hb = 0x8b51f9ddu;  // INIT_B
    unsigned long long val[4];
    for (int i = 0; i < 4; i++) {
        unsigned int w32[2];
        for (int h = 0; h < 2; h++) {
            unsigned int dv = pool[(2 * i + h) & 3];
            dv ^= hb;
            hb *= 0x58f38dedu;  // MULT_B
            dv *= hb;
            dv ^= dv >> 16;
            w32[h] = dv;
        }
        val[i] = (unsigned long long)w32[0] | ((unsigned long long)w32[1] << 32);
    }
    unsigned __int128 initstate = (((unsigned __int128)val[0]) << 64) | val[1];
    unsigned __int128 initseq   = (((unsigned __int128)val[2]) << 64) | val[3];
    g.state = 0;
    g.inc = (initseq << 1) | 1;
    pcg_step(g);
    g.state += initstate;
    pcg_step(g);
    g.has32 = 0;
    g.buf32 = 0;
}

// ---------------- op list (computed on HOST, passed by value) ---------------

#define MAXOPS 64

struct OpsArg {
    int n;
    signed char type[MAXOPS], a[MAXOPS], b[MAXOPS], p[MAXOPS];
};

static void build_ops_host(OpsArg& o) {
    Pcg g;
    pcg_seed42(g);
    int i = 0;
    o.n = 0;
    while (i < 4 && o.n < MAXOPS) {
        if (rng_double(g) > 0.3) {
            int kind = (int)lemire32(g, 3u);   // integers(0,3)
            int w    = (int)lemire32(g, 4u);   // integers(0,4)
            o.type[o.n] = 0; o.a[o.n] = (signed char)kind;
            o.b[o.n] = (signed char)w; o.p[o.n] = (signed char)i;
            o.n++; i++;
        } else {
            int arr[4] = {0, 1, 2, 3};
            for (int ii = 3; ii >= 1; ii--) {
                int jj = (int)rand_interval(g, (unsigned)ii);
                int tmp = arr[ii]; arr[ii] = arr[jj]; arr[jj] = tmp;
            }
            o.type[o.n] = 1; o.a[o.n] = (signed char)arr[0];
            o.b[o.n] = (signed char)arr[1]; o.p[o.n] = 0;
            o.n++;
        }
    }
}

// ---------------- coefficients (duplicated float pairs for FFMA2) -----------

__device__ unsigned long long d_M2[324];  // (m,m) packed per coefficient

// ---------------- setup kernel: fp32, one 256-thread block ------------------

__global__ void __launch_bounds__(256) setup_kernel(const float* __restrict__ rp,
                                                    OpsArg ops) {
    __shared__ float Ur[16][16], Ui[16][16];
    __shared__ float Q[4][16][16];
    int t = threadIdx.x;

    for (int e = t; e < 256; e += 256) {
        Ur[e >> 4][e & 15] = ((e >> 4) == (e & 15)) ? 1.0f : 0.0f;
        Ui[e >> 4][e & 15] = 0.0f;
    }
    __syncthreads();

    for (int o = 0; o < ops.n; o++) {
        if (ops.type[o] == 0) {
            float th = rp[(int)ops.p[o]];
            float ch, sh;
            sincosf(0.5f * th, &sh, &ch);
            int kind = ops.a[o];
            float u00r = ch, u00i = 0, u01r = 0, u01i = 0;
            float u10r = 0,  u10i = 0, u11r = ch, u11i = 0;
            if (kind == 0)      { u01i = -sh; u10i = -sh; }           // RX
            else if (kind == 1) { u01r = -sh; u10r =  sh; }           // RY
            else                { u00i = -sh; u11i =  sh; }           // RZ
            int bit = 1 << (3 - (int)ops.b[o]);
            if (t < 128) {
                int pair = t >> 4, col = t & 15;
                int low = pair & (bit - 1);
                int high = (pair ^ low) << 1;
                int s0 = high | low, s1 = s0 | bit;
                float ar = Ur[s0][col], ai = Ui[s0][col];
                float br = Ur[s1][col], bi = Ui[s1][col];
                Ur[s0][col] = u00r * ar - u00i * ai + u01r * br - u01i * bi;
                Ui[s0][col] = u00r * ai + u00i * ar + u01r * bi + u01i * br;
                Ur[s1][col] = u10r * ar - u10i * ai + u11r * br - u11i * bi;
                Ui[s1][col] = u10r * ai + u10i * ar + u11r * bi + u11i * br;
            }
        } else {
            int cb = 1 << (3 - (int)ops.a[o]);
            int tb = 1 << (3 - (int)ops.b[o]);
            if (t < 64) {
                int pi = t >> 4, col = t & 15;
                int s0 = cb, rr = pi;
                for (int bp = 0; bp < 4; bp++) {
                    int bb = 1 << bp;
                    if (bb == cb || bb == tb) continue;
                    if (rr & 1) s0 |= bb;
                    rr >>= 1;
                }
                int s1 = s0 | tb;
                float xr = Ur[s0][col], xi = Ui[s0][col];
                Ur[s0][col] = Ur[s1][col]; Ui[s0][col] = Ui[s1][col];
                Ur[s1][col] = xr;          Ui[s1][col] = xi;
            }
        }
        __syncthreads();
    }

    // Q_w[a][b] = sum_s sign_w(s) * (Ur[s][a]Ur[s][b] + Ui[s][a]Ui[s][b])
    for (int task = t; task < 1024; task += 256) {
        int w = task >> 8, a = (task >> 4) & 15, b = task & 15;
        int bit = 1 << (3 - w);
        float q = 0;
        for (int s = 0; s < 16; s++) {
            float v = Ur[s][a] * Ur[s][b] + Ui[s][a] * Ui[s][b];
            q += (s & bit) ? -v : v;
        }
        Q[w][a][b] = q;
    }
    __syncthreads();

    // Basis change {cos^2, sin^2, cs} -> {1, C, S}; write duplicated pairs.
    for (int task = t; task < 324; task += 256) {
        int w = task / 81, m = task % 81;
        int mm[4] = { m / 27, (m / 9) % 3, (m / 3) % 3, m % 3 };
        float acc = 0;
        for (int c = 0; c < 16; c++) {
            int a = 0, b = 0;
            float sgn = 1.0f;
            #pragma unroll
            for (int k = 0; k < 4; k++) {
                int sel = (c >> k) & 1;
                int mk = mm[k];
                int i_, j_;
                if (mk == 2) { i_ = sel; j_ = 1 - sel; }
                else         { i_ = sel; j_ = sel; if (mk == 1 && sel == 1) sgn = -sgn; }
                int bitp = 3 - k;
                a |= i_ << bitp;
                b |= j_ << bitp;
            }
            acc += sgn * Q[w][a][b];
        }
        unsigned int bits = __float_as_uint(acc * 0.0625f);
        d_M2[w * 81 + m] = ((unsigned long long)bits << 32) | bits;
    }
}

// ---------------- packed f32x2 helpers --------------------------------------

__device__ __forceinline__ unsigned long long fma2(unsigned long long a,
                                                   unsigned long long b,
                                                   unsigned long long c) {
    unsigned long long d;
    asm("fma.rn.f32x2 %0, %1, %2, %3;" : "=l"(d) : "l"(a), "l"(b), "l"(c));
    return d;
}

__device__ __forceinline__ unsigned long long pack2(float lo, float hi) {
    unsigned long long r;
    asm("mov.b64 %0, {%1, %2};" : "=l"(r) : "f"(lo), "f"(hi));
    return r;
}

__device__ __forceinline__ void unpack2(unsigned long long v, float& lo, float& hi) {
    asm("mov.b64 {%0, %1}, %2;" : "=f"(lo), "=f"(hi) : "l"(v));
}

// ---------------- main kernel: 2 elements/thread, FFMA2 ---------------------

__global__ void __launch_bounds__(256) quanv_kernel(const float* __restrict__ x,
                                                    float* __restrict__ out) {
    __shared__ unsigned long long MsD[324];
    for (int u = threadIdx.x; u < 324; u += 256) MsD[u] = d_M2[u];
    __syncthreads();

    int t = blockIdx.x * 256 + threadIdx.x;          // 0 .. 262143
    int n0 = t * 2;                                   // even element index
    int kk = n0 & 31, j = (n0 >> 5) & 31, i = (n0 >> 10) & 31, b = n0 >> 15;
    const float* xb = x + b * 262144;
    int base = i * 8192 + j * 128 + kk * 2;           // multiple of 4 (kk even)

    // Pair of patches: elem0 at base, elem1 at base+2; all float4 16B-aligned.
    float4 A = *reinterpret_cast<const float4*>(xb + base);          // p0: .x/.z
    float4 B = *reinterpret_cast<const float4*>(xb + base + 4160);   // p1: .x/.z
    float4 C = *reinterpret_cast<const float4*>(xb + base + 64);     // p2: .y/.w
    float4 D = *reinterpret_cast<const float4*>(xb + base + 4096);   // p3: .y/.w

    const float PI = 3.14159265358979323846f;
    float c0a, s0a, c1a, s1a, c2a, s2a, c3a, s3a;     // element 0
    float c0b, s0b, c1b, s1b, c2b, s2b, c3b, s3b;     // element 1
    __sincosf(PI * A.x, &s0a, &c0a);
    __sincosf(PI * B.x, &s1a, &c1a);
    __sincosf(PI * C.y, &s2a, &c2a);
    __sincosf(PI * D.y, &s3a, &c3a);
    __sincosf(PI * A.z, &s0b, &c0b);
    __sincosf(PI * B.z, &s1b, &c1b);
    __sincosf(PI * C.w, &s2b, &c2b);
    __sincosf(PI * D.w, &s3b, &c3b);

    // h = g0 (x) g1 with g = (1, C, S); k = g2 (x) g3. Packed (elem0, elem1).
    unsigned long long H[9], K[9];
    H[0] = pack2(1.f, 1.f);
    H[1] = pack2(c1a, c1b);
    H[2] = pack2(s1a, s1b);
    H[3] = pack2(c0a, c0b);
    H[4] = pack2(c0a * c1a, c0b * c1b);
    H[5] = pack2(c0a * s1a, c0b * s1b);
    H[6] = pack2(s0a, s0b);
    H[7] = pack2(s0a * c1a, s0b * c1b);
    H[8] = pack2(s0a * s1a, s0b * s1b);
    K[0] = pack2(1.f, 1.f);
    K[1] = pack2(c3a, c3b);
    K[2] = pack2(s3a, s3b);
    K[3] = pack2(c2a, c2b);
    K[4] = pack2(c2a * c3a, c2b * c3b);
    K[5] = pack2(c2a * s3a, c2b * s3b);
    K[6] = pack2(s2a, s2b);
    K[7] = pack2(s2a * c3a, s2b * c3b);
    K[8] = pack2(s2a * s3a, s2b * s3b);

    float4 r0, r1;
    float* r0p = &r0.x;
    float* r1p = &r1.x;
    #pragma unroll
    for (int w = 0; w < 4; w++) {
        unsigned long long acc = 0ULL;  // (0.f, 0.f)
        #pragma unroll
        for (int r = 0; r < 9; r++) {
            unsigned long long u = 0ULL;
            #pragma unroll
            for (int c = 0; c < 9; c++)
                u = fma2(MsD[w * 81 + r * 9 + c], K[c], u);
            acc = fma2(H[r], u, acc);
        }
        unpack2(acc, r0p[w], r1p[w]);
    }
    float4* o4 = reinterpret_cast<float4*>(out);
    o4[n0]     = r0;
    o4[n0 + 1] = r1;
}

// ---------------- launch ----------------------------------------------------

extern "C" void kernel_launch(void* const* d_in, const int* in_sizes, int n_in,
                              void* d_out, int out_size) {
    const float* x;
    const float* rp;
    if (n_in >= 2 && in_sizes[0] == 4) {
        rp = (const float*)d_in[0];
        x  = (const float*)d_in[1];
    } else {
        x  = (const float*)d_in[0];
        rp = (const float*)d_in[1];
    }
    OpsArg ops;
    build_ops_host(ops);                 // deterministic per call (seed 42)
    setup_kernel<<<1, 256>>>(rp, ops);
    quanv_kernel<<<1024, 256>>>(x, (float*)d_out);
}